// round 14
// baseline (speedup 1.0000x reference)
#include <cuda_runtime.h>
#include <cstdint>
#include <cstddef>

// ---------------------------------------------------------------------------
// Problem constants
// ---------------------------------------------------------------------------
#define B_ROWS 8192
#define MDIM   256
#define NDIM   512
#define NITER  16

// Persistent-CTA: 128 CTAs x 256 threads (8 warps); CTA owns 64 rows.
// u-space: d_t = s @ G2^T ; u' = s @ Bu^T + WyD ; s = softthr(u').
// Warp tile 64x64: 8 warps span the full 64x512 chunk (1 M-group x 8 N-groups).
// A (packed s) streamed from global via cp.async; B = Bcat rows (3-stage pipe).
#define ROWS 64
#define KC   32            // K elems per block = 16 uint2 k-pairs
#define KP   16
#define THREADS 256

#define BST_U2 (NDIM * KP)          // 8192 uint2 = 64KB per B stage (512 rows)
#define AST_U2 (ROWS * KP)          // 1024 uint2 = 8KB per A stage
#define NST 3
#define SMEM_BYTES ((NST * BST_U2 + NST * AST_U2) * 8)   // 221184
#define PE 516                       // epilogue fp32 staging pitch (mod 32 == 4)

// ---------------------------------------------------------------------------
// Device scratch (static __device__ arrays: allocation-free rule)
// ---------------------------------------------------------------------------
__device__ __align__(1024) uint2 g_Bcatp[1024 * (NDIM / 2)];        // [G2 ; Bu] packed
__device__ __align__(1024) uint2 g_GWp[NDIM * MDIM / 2];            // packed D@W
__device__ __align__(1024) uint2 g_yp[(size_t)B_ROWS * MDIM / 2];   // packed y
__device__ __align__(1024) uint2 g_Sp[(size_t)B_ROWS * (NDIM / 2)]; // packed s
__device__ __align__(1024) float g_WyD[(size_t)B_ROWS * NDIM];      // fp32 addend
__device__ __align__(1024) float g_G1f[NDIM * NDIM];                // fp32 D@S temp

// ---------------------------------------------------------------------------
// PTX helpers (sm_80-level: portable to sm_103 base target)
// ---------------------------------------------------------------------------
__device__ __forceinline__ void cp_async16(uint32_t dst_smem, const void* src) {
    asm volatile("cp.async.cg.shared.global [%0], [%1], 16;"
                 :: "r"(dst_smem), "l"(src) : "memory");
}
__device__ __forceinline__ void cp_commit() {
    asm volatile("cp.async.commit_group;" ::: "memory");
}
template <int N>
__device__ __forceinline__ void cp_wait() {
    asm volatile("cp.async.wait_group %0;" :: "n"(N) : "memory");
}
// pack (u0,u1) into bf16x2 hi + bf16x2 lo (lower half = u0)
__device__ __forceinline__ uint2 pack_split(float u0, float u1) {
    uint32_t hi;
    asm("cvt.rn.bf16x2.f32 %0, %1, %2;" : "=r"(hi) : "f"(u1), "f"(u0));
    float h0 = __uint_as_float(hi << 16);
    float h1 = __uint_as_float(hi & 0xFFFF0000u);
    uint32_t lo;
    asm("cvt.rn.bf16x2.f32 %0, %1, %2;" : "=r"(lo) : "f"(u1 - h1), "f"(u0 - h0));
    return make_uint2(hi, lo);
}
__device__ __forceinline__ void mma_bf16(float* c, const uint32_t* a, const uint32_t* b) {
    asm volatile(
        "mma.sync.aligned.m16n8k16.row.col.f32.bf16.bf16.f32 "
        "{%0,%1,%2,%3},{%4,%5,%6,%7},{%8,%9},{%0,%1,%2,%3};"
        : "+f"(c[0]), "+f"(c[1]), "+f"(c[2]), "+f"(c[3])
        : "r"(a[0]), "r"(a[1]), "r"(a[2]), "r"(a[3]), "r"(b[0]), "r"(b[1]));
}
__device__ __forceinline__ float softthr(float u, float th) {
    return fmaxf(u - th, 0.f) - fmaxf(-u - th, 0.f);
}

// ---------------------------------------------------------------------------
// Precompute kernels
// ---------------------------------------------------------------------------
__global__ void k_small_gemm_f32(const float* __restrict__ A, const float* __restrict__ X,
                                 float* __restrict__ C, int Mcols, int J) {
    __shared__ float As[16][17];
    __shared__ float Xs[16][17];
    int tx = threadIdx.x, ty = threadIdx.y;
    int m = blockIdx.x * 16 + tx;
    int n = blockIdx.y * 16 + ty;
    float acc = 0.f;
    for (int j0 = 0; j0 < J; j0 += 16) {
        As[ty][tx] = A[(size_t)n * J + j0 + tx];
        Xs[ty][tx] = X[(size_t)(j0 + ty) * Mcols + m];
        __syncthreads();
#pragma unroll
        for (int jj = 0; jj < 16; jj++) acc += As[ty][jj] * Xs[jj][tx];
        __syncthreads();
    }
    C[(size_t)n * Mcols + m] = acc;
}

__global__ void k_small_gemm_pack(const float* __restrict__ A, const float* __restrict__ X,
                                  uint2* __restrict__ Cp, int Mcols, int J) {
    __shared__ float As[16][17];
    __shared__ float Xs[16][17];
    int tx = threadIdx.x, ty = threadIdx.y;
    int m = blockIdx.x * 16 + tx;
    int n = blockIdx.y * 16 + ty;
    float acc = 0.f;
    for (int j0 = 0; j0 < J; j0 += 16) {
        As[ty][tx] = A[(size_t)n * J + j0 + tx];
        Xs[ty][tx] = X[(size_t)(j0 + ty) * Mcols + m];
        __syncthreads();
#pragma unroll
        for (int jj = 0; jj < 16; jj++) acc += As[ty][jj] * Xs[jj][tx];
        __syncthreads();
    }
    float other = __shfl_xor_sync(0xffffffffu, acc, 1);
    if (!(tx & 1))
        Cp[(size_t)n * (Mcols / 2) + m / 2] = pack_split(acc, other);
}

// Cp[i][j-pair] = pack( sum_k A[i][k]*Bm[j][k] )  (A,Bm: 512x512 row-major)
__global__ void k_abt_pack(const float* __restrict__ A, const float* __restrict__ Bm,
                           uint2* __restrict__ Cp) {
    __shared__ float As[16][17];
    __shared__ float Bs[16][17];
    int tx = threadIdx.x, ty = threadIdx.y;
    int i = blockIdx.y * 16 + ty;
    int j = blockIdx.x * 16 + tx;
    float acc = 0.f;
    for (int k0 = 0; k0 < NDIM; k0 += 16) {
        As[ty][tx] = A[(size_t)i * NDIM + k0 + tx];
        Bs[ty][tx] = Bm[(size_t)(blockIdx.x * 16 + ty) * NDIM + k0 + tx];
        __syncthreads();
#pragma unroll
        for (int kk = 0; kk < 16; kk++) acc += As[ty][kk] * Bs[tx][kk];
        __syncthreads();
    }
    float other = __shfl_xor_sync(0xffffffffu, acc, 1);
    if (!(tx & 1))
        Cp[(size_t)i * (NDIM / 2) + j / 2] = pack_split(acc, other);
}

// G2p[n][kp] = pack( D[2kp][n], D[2kp+1][n] )
__global__ void k_transpose_pack(const float* __restrict__ D, uint2* __restrict__ G2p) {
    int kp = blockIdx.x * 16 + threadIdx.x;
    int n  = blockIdx.y * 16 + threadIdx.y;
    float u0 = D[(size_t)(2 * kp) * NDIM + n];
    float u1 = D[(size_t)(2 * kp + 1) * NDIM + n];
    G2p[(size_t)n * (NDIM / 2) + kp] = pack_split(u0, u1);
}

// dst[i] = pack(src[2i], src[2i+1])
__global__ void k_split_pack(const float* __restrict__ src, uint2* __restrict__ dst) {
    size_t i = (size_t)blockIdx.x * blockDim.x + threadIdx.x;
    float2 v = ((const float2*)src)[i];
    dst[i] = pack_split(v.x, v.y);
}

// ---------------------------------------------------------------------------
// Persistent ISTA kernel. 8 warps, warp tile 64x64 over the 64x512 chunk.
// ---------------------------------------------------------------------------
__global__ void __launch_bounds__(THREADS, 1) k_ista(
    const float* __restrict__ thr_p, float* __restrict__ out,
    const uint2* __restrict__ Bcatp, const uint2* __restrict__ GWp,
    const uint2* __restrict__ yp, uint2* __restrict__ Sp,
    float* __restrict__ WyD)
{
    extern __shared__ uint2 smu[];
    uint2* BstU = smu;                       // 3 x 8192
    uint2* AstU = smu + NST * BST_U2;        // 3 x 1024
    float* est  = (float*)smu;               // epilogue staging overlay (B stages)

    const int tid  = threadIdx.x;
    const int lane = tid & 31;
    const int warp = tid >> 5;               // 0..7 -> N group
    const int wN = warp;
    const int lr = lane >> 2;                // 0..7
    const int lc = lane & 3;                 // 0..3
    const int r0 = blockIdx.x * ROWS;
    const float th = thr_p[0];
    const size_t slab = (size_t)B_ROWS * NDIM;

    // d0 = 0
    for (int i = tid; i < ROWS * (NDIM / 4); i += THREADS) {
        int r = i >> 7, c4 = i & 127;
        *(float4*)&out[(size_t)(r0 + r) * NDIM + c4 * 4] = make_float4(0, 0, 0, 0);
    }

    // ---- stage fills (16B = 2 uint2; XOR swizzle within 16-uint2 rows) ----
    auto fillB = [&](int st, const uint2* Bg, int ldbp, int kb) {
#pragma unroll
        for (int i = 0; i < 16; ++i) {
            int ch = tid + i * THREADS;              // 0..4095: 512 rows x 8 chunks
            int r = ch >> 3, c2 = ch & 7;
            int cs = (c2 * 2) ^ ((r & 3) << 2);
            uint32_t d = (uint32_t)__cvta_generic_to_shared(&BstU[st * BST_U2 + r * KP + cs]);
            cp_async16(d, Bg + (size_t)r * ldbp + kb * KP + c2 * 2);
        }
    };
    auto fillA = [&](int st, const uint2* Ag, int ldap, int kb) {
#pragma unroll
        for (int i = 0; i < 2; ++i) {
            int ch = tid + i * THREADS;              // 0..511: 64 rows x 8 chunks
            int r = ch >> 3, c2 = ch & 7;
            int cs = (c2 * 2) ^ ((r & 3) << 2);
            uint32_t d = (uint32_t)__cvta_generic_to_shared(&AstU[st * AST_U2 + r * KP + cs]);
            cp_async16(d, Ag + (size_t)r * ldap + kb * KP + c2 * 2);
        }
    };

    // ---- one k-block: 64x64 warp tile, 3-term bf16 MMAs (192 MMA/warp) ----
    auto mma_block = [&](const uint2* sA, const uint2* sB, float (&c)[4][8][4]) {
#pragma unroll
        for (int ks = 0; ks < 2; ++ks) {
            const int kb0 = ks * 8 + lc;
            uint32_t ah[4][4], al[4][4];
#pragma unroll
            for (int mt = 0; mt < 4; ++mt) {
                const int rb = mt * 16 + lr;
                const int sw = (lr & 3) << 2;
                uint2 v0 = sA[rb * KP + (kb0 ^ sw)];
                uint2 v1 = sA[(rb + 8) * KP + (kb0 ^ sw)];
                uint2 v2 = sA[rb * KP + ((kb0 + 4) ^ sw)];
                uint2 v3 = sA[(rb + 8) * KP + ((kb0 + 4) ^ sw)];
                ah[mt][0] = v0.x; al[mt][0] = v0.y;
                ah[mt][1] = v1.x; al[mt][1] = v1.y;
                ah[mt][2] = v2.x; al[mt][2] = v2.y;
                ah[mt][3] = v3.x; al[mt][3] = v3.y;
            }
#pragma unroll
            for (int nt = 0; nt < 8; ++nt) {
                const int nb = wN * 64 + nt * 8 + lr;
                uint2 w0 = sB[nb * KP + (kb0 ^ ((nb & 3) << 2))];
                uint2 w1 = sB[nb * KP + ((kb0 + 4) ^ ((nb & 3) << 2))];
                uint32_t bh[2] = {w0.x, w1.x};
                uint32_t bl[2] = {w0.y, w1.y};
#pragma unroll
                for (int mt = 0; mt < 4; ++mt) {
                    mma_bf16(c[mt][nt], al[mt], bh);
                    mma_bf16(c[mt][nt], ah[mt], bl);
                    mma_bf16(c[mt][nt], ah[mt], bh);
                }
            }
        }
    };

    // ---- full chunk pass: 3-stage pipeline, ONE sync per k-block ----
    auto run_chunk = [&](const uint2* Ag, int ldap, const uint2* Bgc, int ldbp,
                         int KB, float (&c)[4][8][4]) {
        fillA(0, Ag, ldap, 0); fillB(0, Bgc, ldbp, 0); cp_commit();
        fillA(1, Ag, ldap, 1); fillB(1, Bgc, ldbp, 1); cp_commit();
        for (int kb = 0; kb < KB; ++kb) {
            cp_wait<1>();
            __syncthreads();
            if (kb + 2 < KB) {
                fillA((kb + 2) % NST, Ag, ldap, kb + 2);
                fillB((kb + 2) % NST, Bgc, ldbp, kb + 2);
            }
            cp_commit();
            mma_block(&AstU[(kb % NST) * AST_U2], &BstU[(kb % NST) * BST_U2], c);
        }
        cp_wait<0>();
        __syncthreads();
    };

    auto zero_acc = [&](float (&c)[4][8][4]) {
#pragma unroll
        for (int mt = 0; mt < 4; ++mt)
#pragma unroll
            for (int nt = 0; nt < 8; ++nt)
#pragma unroll
                for (int q = 0; q < 4; ++q) c[mt][nt][q] = 0.f;
    };

    // =========================== prestep =================================
    // u0 = y @ GW^T ; WyD = u0 ; Sp = pack(softthr(u0))
    {
        float c[4][8][4];
        zero_acc(c);
        run_chunk(yp + (size_t)r0 * (MDIM / 2), MDIM / 2, GWp, MDIM / 2, MDIM / KC, c);
#pragma unroll
        for (int mt = 0; mt < 4; ++mt)
#pragma unroll
            for (int nt = 0; nt < 8; ++nt) {
                const int col = wN * 64 + nt * 8 + 2 * lc;
#pragma unroll
                for (int half = 0; half < 2; ++half) {
                    const int r = mt * 16 + lr + half * 8;
                    const size_t g = (size_t)(r0 + r) * NDIM + col;
                    float u0 = c[mt][nt][half * 2 + 0];
                    float u1 = c[mt][nt][half * 2 + 1];
                    *(float2*)&WyD[g] = make_float2(u0, u1);
                    Sp[(size_t)(r0 + r) * (NDIM / 2) + (col >> 1)] =
                        pack_split(softthr(u0, th), softthr(u1, th));
                }
            }
        __syncthreads();
    }

    // =========================== iterations ==============================
    for (int t = 1; t <= NITER; ++t) {
        float c[4][8][4];

        // ---- d-pass: d_t = s @ G2^T -> out slab t (est staging) ----
        zero_acc(c);
        run_chunk(Sp + (size_t)r0 * (NDIM / 2), NDIM / 2,
                  Bcatp, NDIM / 2, NDIM / KC, c);
#pragma unroll
        for (int mt = 0; mt < 4; ++mt)
#pragma unroll
            for (int nt = 0; nt < 8; ++nt) {
                const int col = wN * 64 + nt * 8 + 2 * lc;
                const int r = mt * 16 + lr;
                *(float2*)&est[r * PE + col]       = make_float2(c[mt][nt][0], c[mt][nt][1]);
                *(float2*)&est[(r + 8) * PE + col] = make_float2(c[mt][nt][2], c[mt][nt][3]);
            }
        __syncthreads();
        {
            float* dst = out + (size_t)t * slab + (size_t)r0 * NDIM;
            for (int i = tid; i < ROWS * (NDIM / 4); i += THREADS) {
                int r = i >> 7, c4 = i & 127;
                float4 v = *(float4*)&est[r * PE + c4 * 4];
                *(float4*)&dst[(size_t)r * NDIM + c4 * 4] = v;
            }
        }
        __syncthreads();

        if (t == NITER) break;

        // ---- u-pass: u = s @ Bu^T + WyD ; Sp = pack(softthr(u)) ----
        zero_acc(c);
        run_chunk(Sp + (size_t)r0 * (NDIM / 2), NDIM / 2,
                  Bcatp + (size_t)NDIM * (NDIM / 2), NDIM / 2, NDIM / KC, c);
#pragma unroll
        for (int mt = 0; mt < 4; ++mt)
#pragma unroll
            for (int nt = 0; nt < 8; ++nt) {
                const int col = wN * 64 + nt * 8 + 2 * lc;
#pragma unroll
                for (int half = 0; half < 2; ++half) {
                    const int r = mt * 16 + lr + half * 8;
                    const size_t g = (size_t)(r0 + r) * NDIM + col;
                    float2 w = *(const float2*)&WyD[g];
                    float u0 = c[mt][nt][half * 2 + 0] + w.x;
                    float u1 = c[mt][nt][half * 2 + 1] + w.y;
                    Sp[(size_t)(r0 + r) * (NDIM / 2) + (col >> 1)] =
                        pack_split(softthr(u0, th), softthr(u1, th));
                }
            }
        __syncthreads();
    }
}

// ---------------------------------------------------------------------------
// Host side
// ---------------------------------------------------------------------------
extern "C" void kernel_launch(void* const* d_in, const int* in_sizes, int n_in,
                              void* d_out, int out_size) {
    const float* y   = (const float*)d_in[0];
    const float* S   = (const float*)d_in[1];
    const float* W   = (const float*)d_in[2];
    const float* D   = (const float*)d_in[3];
    const float* thr = (const float*)d_in[4];
    float* out = (float*)d_out;

    void *pBcat, *pGW, *pyp, *pSp, *pWyD, *pG1f;
    cudaGetSymbolAddress(&pBcat, g_Bcatp);
    cudaGetSymbolAddress(&pGW, g_GWp);
    cudaGetSymbolAddress(&pyp, g_yp);
    cudaGetSymbolAddress(&pSp, g_Sp);
    cudaGetSymbolAddress(&pWyD, g_WyD);
    cudaGetSymbolAddress(&pG1f, g_G1f);

    cudaFuncSetAttribute(k_ista, cudaFuncAttributeMaxDynamicSharedMemorySize, SMEM_BYTES);

    // Precompute: G1f = D@S (fp32); Bcat rows 0-511 = pack(D^T);
    // Bcat rows 512-1023 = pack(D@S@D^T); GWp = pack(D@W); yp = pack(y).
    k_small_gemm_f32<<<dim3(32, 32), dim3(16, 16)>>>(D, S, (float*)pG1f, NDIM, NDIM);
    k_transpose_pack<<<dim3(16, 32), dim3(16, 16)>>>(D, (uint2*)pBcat);
    k_abt_pack<<<dim3(32, 32), dim3(16, 16)>>>((const float*)pG1f, D,
                                               (uint2*)pBcat + (size_t)NDIM * (NDIM / 2));
    k_small_gemm_pack<<<dim3(16, 32), dim3(16, 16)>>>(D, W, (uint2*)pGW, MDIM, NDIM);
    k_split_pack<<<(B_ROWS * MDIM / 2) / 256, 256>>>(y, (uint2*)pyp);

    // One persistent kernel runs the whole recurrence.
    k_ista<<<B_ROWS / ROWS, THREADS, SMEM_BYTES>>>(
        thr, out, (const uint2*)pBcat, (const uint2*)pGW, (const uint2*)pyp,
        (uint2*)pSp, (float*)pWyD);
}

// round 15
// speedup vs baseline: 1.5736x; 1.5736x over previous
#include <cuda_runtime.h>
#include <cstdint>
#include <cstddef>

// ---------------------------------------------------------------------------
// Problem constants
// ---------------------------------------------------------------------------
#define B_ROWS 8192
#define MDIM   256
#define NDIM   512
#define NITER  16

// Persistent-CTA: 128 CTAs x 1024 threads (32 warps); CTA owns 64 rows.
// u-space recurrence: u' = sigma(u) @ Bu^T + WyD,  d_t = sigma(u) @ G2^T.
// A = sigma(u) (s2) resident in smem. Warp grid 2(M) x 16(N), warp tile 32x16.
#define ROWS 64
#define NC   256
#define KC   32            // K elems per block = 16 uint2 k-pairs
#define KP   16
#define THREADS 1024

#define S_U2   (ROWS * 256)          // 16384 uint2: persistent packed s tile
#define BST_U2 (NC * KP)             // 4096 uint2 per B stage
#define NBST   3
#define SMEM_BYTES ((S_U2 + NBST * BST_U2) * 8)   // 229376
#define PE 260                        // epilogue fp32 staging pitch

// ---------------------------------------------------------------------------
// Device scratch (static __device__ arrays: allocation-free rule)
// ---------------------------------------------------------------------------
__device__ __align__(1024) uint2 g_Bcatp[1024 * (NDIM / 2)];       // [G2 ; Bu] packed
__device__ __align__(1024) uint2 g_GWp[NDIM * MDIM / 2];           // packed D@W
__device__ __align__(1024) uint2 g_yp[(size_t)B_ROWS * MDIM / 2];  // packed y
__device__ __align__(1024) float g_WyD[(size_t)B_ROWS * NDIM];     // fp32 addend
__device__ __align__(1024) float g_Ulo[(size_t)B_ROWS * (NDIM/2)]; // u cols 0-255 scratch
__device__ __align__(1024) float g_G1f[NDIM * NDIM];               // fp32 D@S temp

// ---------------------------------------------------------------------------
// PTX helpers (sm_80-level: portable to sm_103 base target)
// ---------------------------------------------------------------------------
__device__ __forceinline__ void cp_async16(uint32_t dst_smem, const void* src) {
    asm volatile("cp.async.cg.shared.global [%0], [%1], 16;"
                 :: "r"(dst_smem), "l"(src) : "memory");
}
__device__ __forceinline__ void cp_commit() {
    asm volatile("cp.async.commit_group;" ::: "memory");
}
template <int N>
__device__ __forceinline__ void cp_wait() {
    asm volatile("cp.async.wait_group %0;" :: "n"(N) : "memory");
}
// pack (u0,u1) into bf16x2 hi + bf16x2 lo (lower half = u0)
__device__ __forceinline__ uint2 pack_split(float u0, float u1) {
    uint32_t hi;
    asm("cvt.rn.bf16x2.f32 %0, %1, %2;" : "=r"(hi) : "f"(u1), "f"(u0));
    float h0 = __uint_as_float(hi << 16);
    float h1 = __uint_as_float(hi & 0xFFFF0000u);
    uint32_t lo;
    asm("cvt.rn.bf16x2.f32 %0, %1, %2;" : "=r"(lo) : "f"(u1 - h1), "f"(u0 - h0));
    return make_uint2(hi, lo);
}
__device__ __forceinline__ void mma_bf16(float* c, const uint32_t* a, const uint32_t* b) {
    asm volatile(
        "mma.sync.aligned.m16n8k16.row.col.f32.bf16.bf16.f32 "
        "{%0,%1,%2,%3},{%4,%5,%6,%7},{%8,%9},{%0,%1,%2,%3};"
        : "+f"(c[0]), "+f"(c[1]), "+f"(c[2]), "+f"(c[3])
        : "r"(a[0]), "r"(a[1]), "r"(a[2]), "r"(a[3]), "r"(b[0]), "r"(b[1]));
}
__device__ __forceinline__ float softthr(float u, float th) {
    return fmaxf(u - th, 0.f) - fmaxf(-u - th, 0.f);
}

// ---------------------------------------------------------------------------
// Precompute kernels
// ---------------------------------------------------------------------------
__global__ void k_small_gemm_f32(const float* __restrict__ A, const float* __restrict__ X,
                                 float* __restrict__ C, int Mcols, int J) {
    __shared__ float As[16][17];
    __shared__ float Xs[16][17];
    int tx = threadIdx.x, ty = threadIdx.y;
    int m = blockIdx.x * 16 + tx;
    int n = blockIdx.y * 16 + ty;
    float acc = 0.f;
    for (int j0 = 0; j0 < J; j0 += 16) {
        As[ty][tx] = A[(size_t)n * J + j0 + tx];
        Xs[ty][tx] = X[(size_t)(j0 + ty) * Mcols + m];
        __syncthreads();
#pragma unroll
        for (int jj = 0; jj < 16; jj++) acc += As[ty][jj] * Xs[jj][tx];
        __syncthreads();
    }
    C[(size_t)n * Mcols + m] = acc;
}

__global__ void k_small_gemm_pack(const float* __restrict__ A, const float* __restrict__ X,
                                  uint2* __restrict__ Cp, int Mcols, int J) {
    __shared__ float As[16][17];
    __shared__ float Xs[16][17];
    int tx = threadIdx.x, ty = threadIdx.y;
    int m = blockIdx.x * 16 + tx;
    int n = blockIdx.y * 16 + ty;
    float acc = 0.f;
    for (int j0 = 0; j0 < J; j0 += 16) {
        As[ty][tx] = A[(size_t)n * J + j0 + tx];
        Xs[ty][tx] = X[(size_t)(j0 + ty) * Mcols + m];
        __syncthreads();
#pragma unroll
        for (int jj = 0; jj < 16; jj++) acc += As[ty][jj] * Xs[jj][tx];
        __syncthreads();
    }
    float other = __shfl_xor_sync(0xffffffffu, acc, 1);
    if (!(tx & 1))
        Cp[(size_t)n * (Mcols / 2) + m / 2] = pack_split(acc, other);
}

// Cp[i][j-pair] = pack( sum_k A[i][k]*Bm[j][k] )  (A,Bm: 512x512 row-major)
__global__ void k_abt_pack(const float* __restrict__ A, const float* __restrict__ Bm,
                           uint2* __restrict__ Cp) {
    __shared__ float As[16][17];
    __shared__ float Bs[16][17];
    int tx = threadIdx.x, ty = threadIdx.y;
    int i = blockIdx.y * 16 + ty;
    int j = blockIdx.x * 16 + tx;
    float acc = 0.f;
    for (int k0 = 0; k0 < NDIM; k0 += 16) {
        As[ty][tx] = A[(size_t)i * NDIM + k0 + tx];
        Bs[ty][tx] = Bm[(size_t)(blockIdx.x * 16 + ty) * NDIM + k0 + tx];
        __syncthreads();
#pragma unroll
        for (int kk = 0; kk < 16; kk++) acc += As[ty][kk] * Bs[tx][kk];
        __syncthreads();
    }
    float other = __shfl_xor_sync(0xffffffffu, acc, 1);
    if (!(tx & 1))
        Cp[(size_t)i * (NDIM / 2) + j / 2] = pack_split(acc, other);
}

// G2p[n][kp] = pack( D[2kp][n], D[2kp+1][n] )
__global__ void k_transpose_pack(const float* __restrict__ D, uint2* __restrict__ G2p) {
    int kp = blockIdx.x * 16 + threadIdx.x;
    int n  = blockIdx.y * 16 + threadIdx.y;
    float u0 = D[(size_t)(2 * kp) * NDIM + n];
    float u1 = D[(size_t)(2 * kp + 1) * NDIM + n];
    G2p[(size_t)n * (NDIM / 2) + kp] = pack_split(u0, u1);
}

// dst[i] = pack(src[2i], src[2i+1])
__global__ void k_split_pack(const float* __restrict__ src, uint2* __restrict__ dst) {
    size_t i = (size_t)blockIdx.x * blockDim.x + threadIdx.x;
    float2 v = ((const float2*)src)[i];
    dst[i] = pack_split(v.x, v.y);
}

// ---------------------------------------------------------------------------
// Persistent ISTA kernel. 32 warps = 2(M) x 16(N), warp tile 32x16.
// ---------------------------------------------------------------------------
__global__ void __launch_bounds__(THREADS, 1) k_ista(
    const float* __restrict__ thr_p, float* __restrict__ out,
    const uint2* __restrict__ Bcatp, const uint2* __restrict__ GWp,
    const uint2* __restrict__ yp, float* __restrict__ WyD,
    float* __restrict__ Ulo)
{
    extern __shared__ uint2 smu[];
    uint2* s2   = smu;                         // 64 x 256 packed s (swizzled)
    uint2* BstU = smu + S_U2;                  // 3 x 4096
    float* est  = (float*)BstU;                // epilogue fp32 staging overlay

    const int tid  = threadIdx.x;
    const int lane = tid & 31;
    const int warp = tid >> 5;
    const int wM = warp & 1;                   // 0..1 -> rows wM*32
    const int wN = warp >> 1;                  // 0..15 -> cols wN*16
    const int lr = lane >> 2;
    const int lc = lane & 3;
    const int r0 = blockIdx.x * ROWS;
    const float th = thr_p[0];
    const size_t slab = (size_t)B_ROWS * NDIM;

    // d0 = 0
    for (int i = tid; i < ROWS * (NDIM / 4); i += THREADS) {
        int r = i >> 7, c4 = i & 127;
        *(float4*)&out[(size_t)(r0 + r) * NDIM + c4 * 4] = make_float4(0, 0, 0, 0);
    }

    // ---- B stage fill (16B = 2 uint2; XOR swizzle within 16-uint2 rows) ----
    auto fillB = [&](int st, const uint2* Bg, int ldbp, int kb) {
#pragma unroll
        for (int i = 0; i < 2; ++i) {
            int ch = tid + i * THREADS;           // 0..2047: 256 rows x 8 chunks
            int r = ch >> 3, c2 = ch & 7;
            int cs = (c2 * 2) ^ ((r & 3) << 2);
            uint32_t d = (uint32_t)__cvta_generic_to_shared(&BstU[st * BST_U2 + r * KP + cs]);
            cp_async16(d, Bg + (size_t)r * ldbp + kb * KP + c2 * 2);
        }
    };
    // ---- prestep A stages overlay: s2 rows 0-15, second halves (cp 128-255) ----
    auto a_idx = [&](int st, int flat) {
        return (st * 8 + (flat >> 7)) * 256 + 128 + (flat & 127);
    };
    auto fillA_pre = [&](int st, const uint2* Ag, int kb) {
        if (tid < 512) {
            int r = tid >> 3, c2 = tid & 7;        // 64 rows x 8 chunks
            int cs = (c2 * 2) ^ ((r & 3) << 2);
            uint32_t d = (uint32_t)__cvta_generic_to_shared(&s2[a_idx(st, r * KP + cs)]);
            cp_async16(d, Ag + (size_t)r * (MDIM / 2) + kb * KP + c2 * 2);
        }
    };

    // ---- one k-block of 3-term bf16 MMAs: warp tile 32x16 ----
    auto mma_block = [&](auto getA, const uint2* sB, float (&c)[2][2][4]) {
#pragma unroll
        for (int ks = 0; ks < 2; ++ks) {
            const int kb0 = ks * 8 + lc;
            uint32_t ah[2][4], al[2][4], bh[2][2], bl[2][2];
#pragma unroll
            for (int mt = 0; mt < 2; ++mt) {
                const int rb = wM * 32 + mt * 16 + lr;
                uint2 v0 = getA(rb,     kb0);
                uint2 v1 = getA(rb + 8, kb0);
                uint2 v2 = getA(rb,     kb0 + 4);
                uint2 v3 = getA(rb + 8, kb0 + 4);
                ah[mt][0] = v0.x; al[mt][0] = v0.y;
                ah[mt][1] = v1.x; al[mt][1] = v1.y;
                ah[mt][2] = v2.x; al[mt][2] = v2.y;
                ah[mt][3] = v3.x; al[mt][3] = v3.y;
            }
#pragma unroll
            for (int nt = 0; nt < 2; ++nt) {
                const int nb = wN * 16 + nt * 8 + lr;
                uint2 w0 = sB[nb * KP + (kb0 ^ ((nb & 3) << 2))];
                uint2 w1 = sB[nb * KP + ((kb0 + 4) ^ ((nb & 3) << 2))];
                bh[nt][0] = w0.x; bl[nt][0] = w0.y;
                bh[nt][1] = w1.x; bl[nt][1] = w1.y;
            }
#pragma unroll
            for (int mt = 0; mt < 2; ++mt)
#pragma unroll
                for (int nt = 0; nt < 2; ++nt) {
                    mma_bf16(c[mt][nt], al[mt], bh[nt]);
                    mma_bf16(c[mt][nt], ah[mt], bl[nt]);
                    mma_bf16(c[mt][nt], ah[mt], bh[nt]);
                }
        }
    };

    // ---- main-pass chunk: A = s2, 3-stage B pipeline, ONE sync per k-block ----
    auto run_chunk = [&](const uint2* Bgc, float (&c)[2][2][4]) {
        const int KB = NDIM / KC;   // 16
        fillB(0, Bgc, NDIM / 2, 0); cp_commit();
        fillB(1, Bgc, NDIM / 2, 1); cp_commit();
        for (int kb = 0; kb < KB; ++kb) {
            cp_wait<1>();
            __syncthreads();
            if (kb + 2 < KB) fillB((kb + 2) % NBST, Bgc, NDIM / 2, kb + 2);
            cp_commit();
            const int kbase = kb * KP;
            mma_block([&](int r, int kp) {
                int cc = kbase + kp;
                return s2[r * 256 + (cc ^ ((r & 3) << 2))];
            }, &BstU[(kb % NBST) * BST_U2], c);
        }
        __syncthreads();
    };

    auto zero_acc = [&](float (&c)[2][2][4]) {
#pragma unroll
        for (int mt = 0; mt < 2; ++mt)
#pragma unroll
            for (int nt = 0; nt < 2; ++nt)
#pragma unroll
                for (int q = 0; q < 4; ++q) c[mt][nt][q] = 0.f;
    };

    // =========================== prestep =================================
    // WyD = y @ GW^T ; s2 = pack(softthr(WyD)).  A = yp via overlay stages.
    {
        const uint2* Ag = yp + (size_t)r0 * (MDIM / 2);
        for (int h = 0; h < 2; ++h) {
            float c[2][2][4];
            zero_acc(c);
            const uint2* Bgc = GWp + (size_t)(h * NC) * (MDIM / 2);
            fillA_pre(0, Ag, 0);
            fillB(0, Bgc, MDIM / 2, 0);
            cp_commit();
            const int KB = MDIM / KC;   // 8
            for (int kb = 0; kb < KB; ++kb) {
                if (kb + 1 < KB) {
                    fillA_pre((kb + 1) & 1, Ag, kb + 1);
                    fillB((kb + 1) & 1, Bgc, MDIM / 2, kb + 1);
                    cp_commit();
                    cp_wait<1>();
                } else {
                    cp_wait<0>();
                }
                __syncthreads();
                const int st = kb & 1;
                mma_block([&](int r, int kp) {
                    return s2[a_idx(st, r * KP + (kp ^ ((r & 3) << 2)))];
                }, &BstU[st * BST_U2], c);
                __syncthreads();
            }
            // epilogue: WyD = u (fp32) ; s2 = pack(softthr(u))
#pragma unroll
            for (int mt = 0; mt < 2; ++mt)
#pragma unroll
                for (int nt = 0; nt < 2; ++nt) {
                    const int colc = wN * 16 + nt * 8 + 2 * lc;
#pragma unroll
                    for (int half = 0; half < 2; ++half) {
                        const int r = wM * 32 + mt * 16 + lr + half * 8;
                        const int col = h * NC + colc;
                        const size_t g = (size_t)(r0 + r) * NDIM + col;
                        float u0 = c[mt][nt][half * 2 + 0];
                        float u1 = c[mt][nt][half * 2 + 1];
                        *(float2*)&WyD[g] = make_float2(u0, u1);
                        const int cp = col >> 1;
                        s2[r * 256 + (cp ^ ((r & 3) << 2))] =
                            pack_split(softthr(u0, th), softthr(u1, th));
                    }
                }
            __syncthreads();
        }
    }

    // =========================== iterations ==============================
    for (int t = 1; t <= NITER; ++t) {
        float c[2][2][4];

        // ---- chunks 0,1: d_t cols -> out slab t (est staging) ----
        for (int h = 0; h < 2; ++h) {
            zero_acc(c);
            run_chunk(Bcatp + (size_t)(h * NC) * (NDIM / 2), c);
#pragma unroll
            for (int mt = 0; mt < 2; ++mt)
#pragma unroll
                for (int nt = 0; nt < 2; ++nt) {
                    const int colc = wN * 16 + nt * 8 + 2 * lc;
                    const int r = wM * 32 + mt * 16 + lr;
                    *(float2*)&est[r * PE + colc] = make_float2(c[mt][nt][0], c[mt][nt][1]);
                    *(float2*)&est[(r + 8) * PE + colc] = make_float2(c[mt][nt][2], c[mt][nt][3]);
                }
            __syncthreads();
            float* dst = out + (size_t)t * slab + (size_t)r0 * NDIM + h * NC;
            for (int i = tid; i < ROWS * (NC / 4); i += THREADS) {
                int r = i >> 6, c4 = i & 63;
                float4 v = *(float4*)&est[r * PE + c4 * 4];
                *(float4*)&dst[(size_t)r * NDIM + c4 * 4] = v;
            }
            __syncthreads();
        }

        if (t == NITER) break;

        // ---- chunk 2: u cols 0-255, raw fp32 -> Ulo scratch ----
        zero_acc(c);
        run_chunk(Bcatp + (size_t)(2 * NC) * (NDIM / 2), c);
#pragma unroll
        for (int mt = 0; mt < 2; ++mt)
#pragma unroll
            for (int nt = 0; nt < 2; ++nt) {
                const int colc = wN * 16 + nt * 8 + 2 * lc;
#pragma unroll
                for (int half = 0; half < 2; ++half) {
                    const int r = wM * 32 + mt * 16 + lr + half * 8;
                    *(float2*)&Ulo[(size_t)(r0 + r) * (NDIM / 2) + colc] =
                        make_float2(c[mt][nt][half * 2 + 0], c[mt][nt][half * 2 + 1]);
                }
            }
        __syncthreads();

        // ---- chunk 3: u cols 256-511 in regs -> s2 second halves ----
        zero_acc(c);
        run_chunk(Bcatp + (size_t)(3 * NC) * (NDIM / 2), c);
#pragma unroll
        for (int mt = 0; mt < 2; ++mt)
#pragma unroll
            for (int nt = 0; nt < 2; ++nt) {
                const int colc = wN * 16 + nt * 8 + 2 * lc;
#pragma unroll
                for (int half = 0; half < 2; ++half) {
                    const int r = wM * 32 + mt * 16 + lr + half * 8;
                    const size_t g = (size_t)(r0 + r) * NDIM + NC + colc;
                    float2 w = *(const float2*)&WyD[g];
                    float u0 = c[mt][nt][half * 2 + 0] + w.x;
                    float u1 = c[mt][nt][half * 2 + 1] + w.y;
                    const int cp = 128 + (colc >> 1);
                    s2[r * 256 + (cp ^ ((r & 3) << 2))] =
                        pack_split(softthr(u0, th), softthr(u1, th));
                }
            }

        // ---- consume Ulo -> s2 first halves ----
        for (int i = tid; i < ROWS * (NC / 4); i += THREADS) {
            int r = i >> 6, c4 = i & 63;
            float4 v = *(float4*)&Ulo[(size_t)(r0 + r) * (NDIM / 2) + c4 * 4];
            float4 w = *(float4*)&WyD[(size_t)(r0 + r) * NDIM + c4 * 4];
            float s0 = softthr(v.x + w.x, th);
            float s1 = softthr(v.y + w.y, th);
            float s2v = softthr(v.z + w.z, th);
            float s3 = softthr(v.w + w.w, th);
            uint2 p0 = pack_split(s0, s1);
            uint2 p1 = pack_split(s2v, s3);
            int cp = c4 * 2;
            int idx = r * 256 + (cp ^ ((r & 3) << 2));
            *(uint4*)&s2[idx] = make_uint4(p0.x, p0.y, p1.x, p1.y);
        }
        __syncthreads();
    }
}

// ---------------------------------------------------------------------------
// Host side
// ---------------------------------------------------------------------------
extern "C" void kernel_launch(void* const* d_in, const int* in_sizes, int n_in,
                              void* d_out, int out_size) {
    const float* y   = (const float*)d_in[0];
    const float* S   = (const float*)d_in[1];
    const float* W   = (const float*)d_in[2];
    const float* D   = (const float*)d_in[3];
    const float* thr = (const float*)d_in[4];
    float* out = (float*)d_out;

    void *pBcat, *pGW, *pyp, *pWyD, *pUlo, *pG1f;
    cudaGetSymbolAddress(&pBcat, g_Bcatp);
    cudaGetSymbolAddress(&pGW, g_GWp);
    cudaGetSymbolAddress(&pyp, g_yp);
    cudaGetSymbolAddress(&pWyD, g_WyD);
    cudaGetSymbolAddress(&pUlo, g_Ulo);
    cudaGetSymbolAddress(&pG1f, g_G1f);

    cudaFuncSetAttribute(k_ista, cudaFuncAttributeMaxDynamicSharedMemorySize, SMEM_BYTES);

    // Precompute: G1f = D@S (fp32); Bcat rows 0-511 = pack(D^T);
    // Bcat rows 512-1023 = pack(D@S@D^T); GWp = pack(D@W); yp = pack(y).
    k_small_gemm_f32<<<dim3(32, 32), dim3(16, 16)>>>(D, S, (float*)pG1f, NDIM, NDIM);
    k_transpose_pack<<<dim3(16, 32), dim3(16, 16)>>>(D, (uint2*)pBcat);
    k_abt_pack<<<dim3(32, 32), dim3(16, 16)>>>((const float*)pG1f, D,
                                               (uint2*)pBcat + (size_t)NDIM * (NDIM / 2));
    k_small_gemm_pack<<<dim3(16, 32), dim3(16, 16)>>>(D, W, (uint2*)pGW, MDIM, NDIM);
    k_split_pack<<<(B_ROWS * MDIM / 2) / 256, 256>>>(y, (uint2*)pyp);

    // One persistent kernel runs the whole recurrence.
    k_ista<<<B_ROWS / ROWS, THREADS, SMEM_BYTES>>>(
        thr, out, (const uint2*)pBcat, (const uint2*)pGW, (const uint2*)pyp,
        (float*)pWyD, (float*)pUlo);
}

// round 16
// speedup vs baseline: 1.9861x; 1.2622x over previous
#include <cuda_runtime.h>
#include <cstdint>
#include <cstddef>

// ---------------------------------------------------------------------------
// Problem constants
// ---------------------------------------------------------------------------
#define B_ROWS 8192
#define MDIM   256
#define NDIM   512
#define NITER  16

// Persistent-CTA: 128 CTAs x 512 threads (16 warps); CTA owns 64 rows.
// u-space recurrence: u' = s @ Bu^T + WyD,  d_t = s @ G2^T, s = softthr(u).
// A = s resident in smem as bf16x2 hi/lo PLANES; fragment loads via ldmatrix.x4.
// Warp grid 2(M) x 8(N), warp tile 32x32. 3-stage B pipeline, 1 sync/k-block.
#define ROWS 64
#define NC   256
#define KC   32              // K elems per block = 16 u32 pairs = 4 k8-chunks
#define KP   16              // u32 (bf16x2) per row per k-block
#define THREADS 512

// smem (u32 units): s2 planes + 3 B stages (each hi 4096 + lo 4096 u32)
#define S2H_OFF 0
#define S2L_OFF 16384
#define BST_OFF 32768
#define BST_U32 8192          // per stage (hi+lo)
#define SMEM_BYTES ((32768 + 3 * BST_U32) * 4)   // 229376
#define PE 260                // epilogue fp32 staging pitch

// ---------------------------------------------------------------------------
// Device scratch (static __device__ arrays: allocation-free rule)
// ---------------------------------------------------------------------------
__device__ __align__(1024) uint32_t g_BcatH[1024 * 256];           // [G2;Bu] hi plane
__device__ __align__(1024) uint32_t g_BcatL[1024 * 256];           // [G2;Bu] lo plane
__device__ __align__(1024) uint2 g_GWp[NDIM * MDIM / 2];           // packed D@W (interleaved)
__device__ __align__(1024) uint2 g_yp[(size_t)B_ROWS * MDIM / 2];  // packed y (interleaved)
__device__ __align__(1024) float g_WyD[(size_t)B_ROWS * NDIM];     // fp32 addend
__device__ __align__(1024) float g_Ulo[(size_t)B_ROWS * (NDIM/2)]; // u cols 0-255 scratch
__device__ __align__(1024) float g_G1f[NDIM * NDIM];               // fp32 D@S temp

// ---------------------------------------------------------------------------
// PTX helpers (sm_80-level: portable to sm_103 base target)
// ---------------------------------------------------------------------------
__device__ __forceinline__ void cp_async16(uint32_t dst_smem, const void* src) {
    asm volatile("cp.async.cg.shared.global [%0], [%1], 16;"
                 :: "r"(dst_smem), "l"(src) : "memory");
}
__device__ __forceinline__ void cp_commit() {
    asm volatile("cp.async.commit_group;" ::: "memory");
}
template <int N>
__device__ __forceinline__ void cp_wait() {
    asm volatile("cp.async.wait_group %0;" :: "n"(N) : "memory");
}
__device__ __forceinline__ void ldsm_x4(uint32_t& r0, uint32_t& r1, uint32_t& r2,
                                        uint32_t& r3, uint32_t saddr) {
    asm volatile("ldmatrix.sync.aligned.m8n8.x4.shared.b16 {%0,%1,%2,%3}, [%4];"
                 : "=r"(r0), "=r"(r1), "=r"(r2), "=r"(r3) : "r"(saddr));
}
// pack (u0,u1) into bf16x2 hi + bf16x2 lo (lower half = u0)
__device__ __forceinline__ uint2 pack_split(float u0, float u1) {
    uint32_t hi;
    asm("cvt.rn.bf16x2.f32 %0, %1, %2;" : "=r"(hi) : "f"(u1), "f"(u0));
    float h0 = __uint_as_float(hi << 16);
    float h1 = __uint_as_float(hi & 0xFFFF0000u);
    uint32_t lo;
    asm("cvt.rn.bf16x2.f32 %0, %1, %2;" : "=r"(lo) : "f"(u1 - h1), "f"(u0 - h0));
    return make_uint2(hi, lo);
}
__device__ __forceinline__ void mma_bf16(float* c, const uint32_t* a, const uint32_t* b) {
    asm volatile(
        "mma.sync.aligned.m16n8k16.row.col.f32.bf16.bf16.f32 "
        "{%0,%1,%2,%3},{%4,%5,%6,%7},{%8,%9},{%0,%1,%2,%3};"
        : "+f"(c[0]), "+f"(c[1]), "+f"(c[2]), "+f"(c[3])
        : "r"(a[0]), "r"(a[1]), "r"(a[2]), "r"(a[3]), "r"(b[0]), "r"(b[1]));
}
__device__ __forceinline__ float softthr(float u, float th) {
    return fmaxf(u - th, 0.f) - fmaxf(-u - th, 0.f);
}

// ---------------------------------------------------------------------------
// Precompute kernels
// ---------------------------------------------------------------------------
__global__ void k_small_gemm_f32(const float* __restrict__ A, const float* __restrict__ X,
                                 float* __restrict__ C, int Mcols, int J) {
    __shared__ float As[16][17];
    __shared__ float Xs[16][17];
    int tx = threadIdx.x, ty = threadIdx.y;
    int m = blockIdx.x * 16 + tx;
    int n = blockIdx.y * 16 + ty;
    float acc = 0.f;
    for (int j0 = 0; j0 < J; j0 += 16) {
        As[ty][tx] = A[(size_t)n * J + j0 + tx];
        Xs[ty][tx] = X[(size_t)(j0 + ty) * Mcols + m];
        __syncthreads();
#pragma unroll
        for (int jj = 0; jj < 16; jj++) acc += As[ty][jj] * Xs[jj][tx];
        __syncthreads();
    }
    C[(size_t)n * Mcols + m] = acc;
}

__global__ void k_small_gemm_pack(const float* __restrict__ A, const float* __restrict__ X,
                                  uint2* __restrict__ Cp, int Mcols, int J) {
    __shared__ float As[16][17];
    __shared__ float Xs[16][17];
    int tx = threadIdx.x, ty = threadIdx.y;
    int m = blockIdx.x * 16 + tx;
    int n = blockIdx.y * 16 + ty;
    float acc = 0.f;
    for (int j0 = 0; j0 < J; j0 += 16) {
        As[ty][tx] = A[(size_t)n * J + j0 + tx];
        Xs[ty][tx] = X[(size_t)(j0 + ty) * Mcols + m];
        __syncthreads();
#pragma unroll
        for (int jj = 0; jj < 16; jj++) acc += As[ty][jj] * Xs[jj][tx];
        __syncthreads();
    }
    float other = __shfl_xor_sync(0xffffffffu, acc, 1);
    if (!(tx & 1))
        Cp[(size_t)n * (Mcols / 2) + m / 2] = pack_split(acc, other);
}

// Bcat rows [0,512): H/L[n][kp] = planes of pack( D[2kp][n], D[2kp+1][n] )
__global__ void k_transpose_pack_pl(const float* __restrict__ D,
                                    uint32_t* __restrict__ H, uint32_t* __restrict__ L) {
    int kp = blockIdx.x * 16 + threadIdx.x;   // 0..255
    int n  = blockIdx.y * 16 + threadIdx.y;   // 0..511
    uint2 p = pack_split(D[(size_t)(2 * kp) * NDIM + n],
                         D[(size_t)(2 * kp + 1) * NDIM + n]);
    H[(size_t)n * 256 + kp] = p.x;
    L[(size_t)n * 256 + kp] = p.y;
}

// Bcat rows [512,1024): planes of pack_j( sum_k A[i][k]*Bm[j][k] )
__global__ void k_abt_pack_pl(const float* __restrict__ A, const float* __restrict__ Bm,
                              uint32_t* __restrict__ H, uint32_t* __restrict__ L) {
    __shared__ float As[16][17];
    __shared__ float Bs[16][17];
    int tx = threadIdx.x, ty = threadIdx.y;
    int i = blockIdx.y * 16 + ty;
    int j = blockIdx.x * 16 + tx;
    float acc = 0.f;
    for (int k0 = 0; k0 < NDIM; k0 += 16) {
        As[ty][tx] = A[(size_t)i * NDIM + k0 + tx];
        Bs[ty][tx] = Bm[(size_t)(blockIdx.x * 16 + ty) * NDIM + k0 + tx];
        __syncthreads();
#pragma unroll
        for (int kk = 0; kk < 16; kk++) acc += As[ty][kk] * Bs[tx][kk];
        __syncthreads();
    }
    float other = __shfl_xor_sync(0xffffffffu, acc, 1);
    if (!(tx & 1)) {
        uint2 p = pack_split(acc, other);
        H[(size_t)i * 256 + j / 2] = p.x;
        L[(size_t)i * 256 + j / 2] = p.y;
    }
}

// dst[i] = pack(src[2i], src[2i+1])  (interleaved, prestep inputs)
__global__ void k_split_pack(const float* __restrict__ src, uint2* __restrict__ dst) {
    size_t i = (size_t)blockIdx.x * blockDim.x + threadIdx.x;
    float2 v = ((const float2*)src)[i];
    dst[i] = pack_split(v.x, v.y);
}

// ---------------------------------------------------------------------------
// Persistent ISTA kernel. 16 warps = 2(M) x 8(N), warp tile 32x32, ldmatrix.
// ---------------------------------------------------------------------------
__global__ void __launch_bounds__(THREADS, 1) k_ista(
    const float* __restrict__ thr_p, float* __restrict__ out,
    const uint32_t* __restrict__ BcatH, const uint32_t* __restrict__ BcatL,
    const uint2* __restrict__ GWp, const uint2* __restrict__ yp,
    float* __restrict__ WyD, float* __restrict__ Ulo)
{
    extern __shared__ uint32_t smw[];
    uint32_t* s2h = smw + S2H_OFF;            // 64 x 256 u32 (hi plane, swizzled)
    uint32_t* s2l = smw + S2L_OFF;            // 64 x 256 u32 (lo plane, swizzled)
    uint32_t* Bst = smw + BST_OFF;            // 3 stages x (hi 4096 | lo 4096)
    float* est = (float*)Bst;                 // epilogue fp32 staging overlay
    uint2* preB = (uint2*)Bst;                // prestep B stages 0,1 (uint2 view)
    uint2* preA = (uint2*)(Bst + 2 * BST_U32);// prestep A overlay (stage-2 region)

    const uint32_t s2h_sa = (uint32_t)__cvta_generic_to_shared(s2h);
    const uint32_t s2l_sa = (uint32_t)__cvta_generic_to_shared(s2l);
    const uint32_t bst_sa = (uint32_t)__cvta_generic_to_shared(Bst);

    const int tid  = threadIdx.x;
    const int lane = tid & 31;
    const int warp = tid >> 5;
    const int wM = warp & 1;                   // rows wM*32
    const int wN = warp >> 1;                  // cols wN*32
    const int lr = lane >> 2;
    const int lc = lane & 3;
    const int r0 = blockIdx.x * ROWS;
    const float th = thr_p[0];
    const size_t slab = (size_t)B_ROWS * NDIM;

    // ldmatrix lane decomposition (tile t = lane/8, row-in-tile = lane%7+1... lane&7)
    const int lt  = lane >> 3;                 // 0..3
    const int ltr = lane & 7;                  // 0..7
    const int rowA0 = wM * 32 + ((lt & 1) << 3) + ltr;   // + mt*16
    const int nB0   = wN * 32 + ((lt & 1) << 3) + ltr;   // + p*16
    const int gsel  = lt >> 1;                 // 0/1: k8 within k16

    // d0 = 0
    for (int i = tid; i < ROWS * (NDIM / 4); i += THREADS) {
        int r = i >> 7, c4 = i & 127;
        *(float4*)&out[(size_t)(r0 + r) * NDIM + c4 * 4] = make_float4(0, 0, 0, 0);
    }

    // ---- main B stage fill: planes, swizzle chunk c -> c ^ ((r>>1)&3) ----
    auto fillB = [&](int st, int brow0, int kb) {
#pragma unroll
        for (int i = 0; i < 4; ++i) {
            int ch = tid + i * THREADS;           // 0..2047
            int pl = ch >> 10;                    // plane
            int r  = (ch >> 2) & 255;
            int c  = ch & 3;
            const uint32_t* src = (pl ? BcatL : BcatH) +
                (size_t)(brow0 + r) * 256 + kb * KP + c * 4;
            uint32_t doff = (BST_OFF + st * BST_U32 + pl * 4096 +
                             r * KP + ((c ^ ((r >> 1) & 3)) << 2)) * 4;
            cp_async16((uint32_t)__cvta_generic_to_shared(smw) + doff, src);
        }
    };

    // ---- main mma: warp tile 32x32 via ldmatrix.x4 on planes ----
    auto mma_new = [&](int kb, int st, float (&c)[2][4][4]) {
        const uint32_t bh_sa = bst_sa + (st * BST_U32) * 4;
        const uint32_t bl_sa = bh_sa + 4096 * 4;
#pragma unroll
        for (int ks = 0; ks < 2; ++ks) {
            uint32_t ah[2][4], al[2][4], bh[4][2], bl[4][2];
#pragma unroll
            for (int mt = 0; mt < 2; ++mt) {
                const int row = rowA0 + mt * 16;
                const int gg = kb * 4 + ks * 2 + gsel;
                const uint32_t off = ((row << 8) + (((gg ^ (row & 7))) << 2)) * 4;
                ldsm_x4(ah[mt][0], ah[mt][1], ah[mt][2], ah[mt][3], s2h_sa + off);
                ldsm_x4(al[mt][0], al[mt][1], al[mt][2], al[mt][3], s2l_sa + off);
            }
#pragma unroll
            for (int p = 0; p < 2; ++p) {
                const int n = nB0 + p * 16;
                const int g = ks * 2 + gsel;
                const uint32_t off = ((n << 4) + ((g ^ ((n >> 1) & 3)) << 2)) * 4;
                uint32_t r0r, r1r, r2r, r3r;
                ldsm_x4(r0r, r1r, r2r, r3r, bh_sa + off);
                bh[2 * p][0] = r0r; bh[2 * p + 1][0] = r1r;
                bh[2 * p][1] = r2r; bh[2 * p + 1][1] = r3r;
                ldsm_x4(r0r, r1r, r2r, r3r, bl_sa + off);
                bl[2 * p][0] = r0r; bl[2 * p + 1][0] = r1r;
                bl[2 * p][1] = r2r; bl[2 * p + 1][1] = r3r;
            }
#pragma unroll
            for (int mt = 0; mt < 2; ++mt)
#pragma unroll
                for (int nt = 0; nt < 4; ++nt) {
                    mma_bf16(c[mt][nt], al[mt], bh[nt]);
                    mma_bf16(c[mt][nt], ah[mt], bl[nt]);
                    mma_bf16(c[mt][nt], ah[mt], bh[nt]);
                }
        }
    };

    // ---- main-pass chunk: A = s2 planes, 3-stage B pipe, ONE sync/k-block ----
    auto run_chunk = [&](int brow0, float (&c)[2][4][4]) {
        const int KB = NDIM / KC;   // 16
        fillB(0, brow0, 0); cp_commit();
        fillB(1, brow0, 1); cp_commit();
        for (int kb = 0; kb < KB; ++kb) {
            cp_wait<1>();
            __syncthreads();
            if (kb + 2 < KB) fillB((kb + 2) % 3, brow0, kb + 2);
            cp_commit();
            mma_new(kb, kb % 3, c);
        }
        __syncthreads();
    };

    auto zero_acc = [&](float (&c)[2][4][4]) {
#pragma unroll
        for (int mt = 0; mt < 2; ++mt)
#pragma unroll
            for (int nt = 0; nt < 4; ++nt)
#pragma unroll
                for (int q = 0; q < 4; ++q) c[mt][nt][q] = 0.f;
    };

    // s2 plane store of packed pair at (row r, pair-col cp)
    auto s2_store = [&](int r, int cp, uint2 p) {
        int idx = r * 256 + (((cp >> 2) ^ (r & 7)) << 2) + (cp & 3);
        s2h[idx] = p.x;
        s2l[idx] = p.y;
    };

    // =========================== prestep =================================
    // WyD = y @ GW^T ; s2 = pack(softthr(WyD)).  Manual uint2 path on scratch.
    {
        const uint2* Ag = yp + (size_t)r0 * (MDIM / 2);
        auto fillB_pre = [&](int st, const uint2* Bg, int kb) {
#pragma unroll
            for (int i = 0; i < 4; ++i) {
                int ch = tid + i * THREADS;       // 256 rows x 8 chunks
                int r = ch >> 3, c2 = ch & 7;
                int cs = (c2 * 2) ^ ((r & 3) << 2);
                uint32_t d = (uint32_t)__cvta_generic_to_shared(
                    &preB[st * 4096 + r * KP + cs]);
                cp_async16(d, Bg + (size_t)r * (MDIM / 2) + kb * KP + c2 * 2);
            }
        };
        auto fillA_pre = [&](int st, int kb) {
            int r = tid >> 3, c2 = tid & 7;       // 64 rows x 8 chunks
            int cs = (c2 * 2) ^ ((r & 3) << 2);
            uint32_t d = (uint32_t)__cvta_generic_to_shared(
                &preA[st * 1024 + r * KP + cs]);
            cp_async16(d, Ag + (size_t)r * (MDIM / 2) + kb * KP + c2 * 2);
        };
        auto mma_old = [&](const uint2* sA, const uint2* sB, float (&c)[2][4][4]) {
#pragma unroll
            for (int ks = 0; ks < 2; ++ks) {
                const int kb0 = ks * 8 + lc;
                uint32_t ah[2][4], al[2][4], bh[4][2], bl[4][2];
#pragma unroll
                for (int mt = 0; mt < 2; ++mt) {
                    const int rb = wM * 32 + mt * 16 + lr;
                    uint2 v0 = sA[rb * KP + (kb0 ^ ((rb & 3) << 2))];
                    uint2 v1 = sA[(rb + 8) * KP + (kb0 ^ (((rb + 8) & 3) << 2))];
                    uint2 v2 = sA[rb * KP + ((kb0 + 4) ^ ((rb & 3) << 2))];
                    uint2 v3 = sA[(rb + 8) * KP + ((kb0 + 4) ^ (((rb + 8) & 3) << 2))];
                    ah[mt][0] = v0.x; al[mt][0] = v0.y;
                    ah[mt][1] = v1.x; al[mt][1] = v1.y;
                    ah[mt][2] = v2.x; al[mt][2] = v2.y;
                    ah[mt][3] = v3.x; al[mt][3] = v3.y;
                }
#pragma unroll
                for (int nt = 0; nt < 4; ++nt) {
                    const int nb = wN * 32 + nt * 8 + lr;
                    uint2 w0 = sB[nb * KP + (kb0 ^ ((nb & 3) << 2))];
                    uint2 w1 = sB[nb * KP + ((kb0 + 4) ^ ((nb & 3) << 2))];
                    bh[nt][0] = w0.x; bl[nt][0] = w0.y;
                    bh[nt][1] = w1.x; bl[nt][1] = w1.y;
                }
#pragma unroll
                for (int mt = 0; mt < 2; ++mt)
#pragma unroll
                    for (int nt = 0; nt < 4; ++nt) {
                        mma_bf16(c[mt][nt], al[mt], bh[nt]);
                        mma_bf16(c[mt][nt], ah[mt], bl[nt]);
                        mma_bf16(c[mt][nt], ah[mt], bh[nt]);
                    }
            }
        };

        for (int h = 0; h < 2; ++h) {
            float c[2][4][4];
            zero_acc(c);
            const uint2* Bgc = GWp + (size_t)(h * NC) * (MDIM / 2);
            fillA_pre(0, 0);
            fillB_pre(0, Bgc, 0);
            cp_commit();
            const int KB = MDIM / KC;   // 8
            for (int kb = 0; kb < KB; ++kb) {
                if (kb + 1 < KB) {
                    fillA_pre((kb + 1) & 1, kb + 1);
                    fillB_pre((kb + 1) & 1, Bgc, kb + 1);
                    cp_commit();
                    cp_wait<1>();
                } else {
                    cp_wait<0>();
                }
                __syncthreads();
                mma_old(&preA[(kb & 1) * 1024], &preB[(kb & 1) * 4096], c);
                __syncthreads();
            }
#pragma unroll
            for (int mt = 0; mt < 2; ++mt)
#pragma unroll
                for (int nt = 0; nt < 4; ++nt) {
                    const int colc = wN * 32 + nt * 8 + 2 * lc;
#pragma unroll
                    for (int half = 0; half < 2; ++half) {
                        const int r = wM * 32 + mt * 16 + lr + half * 8;
                        const int col = h * NC + colc;
                        const size_t g = (size_t)(r0 + r) * NDIM + col;
                        float u0 = c[mt][nt][half * 2 + 0];
                        float u1 = c[mt][nt][half * 2 + 1];
                        *(float2*)&WyD[g] = make_float2(u0, u1);
                        s2_store(r, col >> 1, pack_split(softthr(u0, th), softthr(u1, th)));
                    }
                }
            __syncthreads();
        }
    }

    // =========================== iterations ==============================
    for (int t = 1; t <= NITER; ++t) {
        float c[2][4][4];

        // ---- chunks 0,1: d_t cols -> out slab t (est staging) ----
        for (int h = 0; h < 2; ++h) {
            zero_acc(c);
            run_chunk(h * NC, c);
#pragma unroll
            for (int mt = 0; mt < 2; ++mt)
#pragma unroll
                for (int nt = 0; nt < 4; ++nt) {
                    const int colc = wN * 32 + nt * 8 + 2 * lc;
                    const int r = wM * 32 + mt * 16 + lr;
                    *(float2*)&est[r * PE + colc] = make_float2(c[mt][nt][0], c[mt][nt][1]);
                    *(float2*)&est[(r + 8) * PE + colc] = make_float2(c[mt][nt][2], c[mt][nt][3]);
                }
            __syncthreads();
            float* dst = out + (size_t)t * slab + (size_t)r0 * NDIM + h * NC;
            for (int i = tid; i < ROWS * (NC / 4); i += THREADS) {
                int r = i >> 6, c4 = i & 63;
                float4 v = *(float4*)&est[r * PE + c4 * 4];
                *(float4*)&dst[(size_t)r * NDIM + c4 * 4] = v;
            }
            __syncthreads();
        }

        if (t == NITER) break;

        // ---- chunk 2: u cols 0-255, raw fp32 -> Ulo scratch ----
        zero_acc(c);
        run_chunk(2 * NC, c);
#pragma unroll
        for (int mt = 0; mt < 2; ++mt)
#pragma unroll
            for (int nt = 0; nt < 4; ++nt) {
                const int colc = wN * 32 + nt * 8 + 2 * lc;
#pragma unroll
                for (int half = 0; half < 2; ++half) {
                    const int r = wM * 32 + mt * 16 + lr + half * 8;
                    *(float2*)&Ulo[(size_t)(r0 + r) * (NDIM / 2) + colc] =
                        make_float2(c[mt][nt][half * 2 + 0], c[mt][nt][half * 2 + 1]);
                }
            }
        __syncthreads();

        // ---- chunk 3: u cols 256-511 in regs -> s2 second halves ----
        zero_acc(c);
        run_chunk(3 * NC, c);
#pragma unroll
        for (int mt = 0; mt < 2; ++mt)
#pragma unroll
            for (int nt = 0; nt < 4; ++nt) {
                const int colc = wN * 32 + nt * 8 + 2 * lc;
#pragma unroll
                for (int half = 0; half < 2; ++half) {
                    const int r = wM * 32 + mt * 16 + lr + half * 8;
                    const size_t g = (size_t)(r0 + r) * NDIM + NC + colc;
                    float2 w = *(const float2*)&WyD[g];
                    float u0 = c[mt][nt][half * 2 + 0] + w.x;
                    float u1 = c[mt][nt][half * 2 + 1] + w.y;
                    s2_store(r, (NC + colc) >> 1,
                             pack_split(softthr(u0, th), softthr(u1, th)));
                }
            }

        // ---- consume Ulo -> s2 first halves ----
        for (int i = tid; i < ROWS * (NC / 4); i += THREADS) {
            int r = i >> 6, c4 = i & 63;                 // kp pair base = 2*c4
            float4 v = *(float4*)&Ulo[(size_t)(r0 + r) * (NDIM / 2) + c4 * 4];
            float4 w = *(float4*)&WyD[(size_t)(r0 + r) * NDIM + c4 * 4];
            uint2 p0 = pack_split(softthr(v.x + w.x, th), softthr(v.y + w.y, th));
            uint2 p1 = pack_split(softthr(v.z + w.z, th), softthr(v.w + w.w, th));
            int idx = r * 256 + (((c4 >> 1) ^ (r & 7)) << 2) + ((c4 & 1) * 2);
            *(uint2*)&s2h[idx] = make_uint2(p0.x, p1.x);
            *(uint2*)&s2l[idx] = make_uint2(p0.y, p1.y);
        }
        __syncthreads();
    }
}

// ---------------------------------------------------------------------------
// Host side
// ---------------------------------------------------------------------------
extern "C" void kernel_launch(void* const* d_in, const int* in_sizes, int n_in,
                              void* d_out, int out_size) {
    const float* y   = (const float*)d_in[0];
    const float* S   = (const float*)d_in[1];
    const float* W   = (const float*)d_in[2];
    const float* D   = (const float*)d_in[3];
    const float* thr = (const float*)d_in[4];
    float* out = (float*)d_out;

    void *pBH, *pBL, *pGW, *pyp, *pWyD, *pUlo, *pG1f;
    cudaGetSymbolAddress(&pBH, g_BcatH);
    cudaGetSymbolAddress(&pBL, g_BcatL);
    cudaGetSymbolAddress(&pGW, g_GWp);
    cudaGetSymbolAddress(&pyp, g_yp);
    cudaGetSymbolAddress(&pWyD, g_WyD);
    cudaGetSymbolAddress(&pUlo, g_Ulo);
    cudaGetSymbolAddress(&pG1f, g_G1f);
    uint32_t* BH = (uint32_t*)pBH;
    uint32_t* BL = (uint32_t*)pBL;

    cudaFuncSetAttribute(k_ista, cudaFuncAttributeMaxDynamicSharedMemorySize, SMEM_BYTES);

    // Precompute: G1f = D@S; Bcat planes rows 0-511 = D^T, rows 512-1023 = D@S@D^T;
    // GWp = pack(D@W) interleaved; yp = pack(y) interleaved.
    k_small_gemm_f32<<<dim3(32, 32), dim3(16, 16)>>>(D, S, (float*)pG1f, NDIM, NDIM);
    k_transpose_pack_pl<<<dim3(16, 32), dim3(16, 16)>>>(D, BH, BL);
    k_abt_pack_pl<<<dim3(32, 32), dim3(16, 16)>>>((const float*)pG1f, D,
                                                  BH + (size_t)NDIM * 256,
                                                  BL + (size_t)NDIM * 256);
    k_small_gemm_pack<<<dim3(16, 32), dim3(16, 16)>>>(D, W, (uint2*)pGW, MDIM, NDIM);
    k_split_pack<<<(B_ROWS * MDIM / 2) / 256, 256>>>(y, (uint2*)pyp);

    // One persistent kernel runs the whole recurrence.
    k_ista<<<B_ROWS / ROWS, THREADS, SMEM_BYTES>>>(
        thr, out, BH, BL, (const uint2*)pGW, (const uint2*)pyp,
        (float*)pWyD, (float*)pUlo);
}